// round 1
// baseline (speedup 1.0000x reference)
#include <cuda_runtime.h>
#include <cuda_bf16.h>
#include <cstdint>

// Problem constants (fixed shapes per reference)
#define NV 100000      // vertices
#define TT 128         // temporal depth
#define EE 1600000     // edges
#define KK 9           // conv kernel
#define LL 3           // layers

// ---------------- scratch (device globals; no runtime allocation) -----------
__device__ float g_h[(size_t)NV * TT];     // conv output per layer
__device__ float g_x[(size_t)NV * TT];     // layer activation (ping target)
__device__ int   g_deg[NV];                // in-degree histogram
__device__ int   g_fill[NV];               // fill cursors for CSR build
__device__ int   g_rowptr[NV + 1];         // CSR row pointers (by dst)
__device__ int   g_col[EE];                // CSR column indices (src per dst)
__device__ int   g_blocksum[256];          // scan partials
__device__ int   g_blockoff[256];          // scanned partials

// ---------------- CSR build --------------------------------------------------
__global__ void zero_counts_kernel() {
    int i = blockIdx.x * blockDim.x + threadIdx.x;
    if (i < NV) { g_deg[i] = 0; g_fill[i] = 0; }
}

__global__ void hist_kernel(const int* __restrict__ dst) {
    int e = blockIdx.x * blockDim.x + threadIdx.x;
    if (e < EE) atomicAdd(&g_deg[dst[e]], 1);
}

// 512-thread blocks over N+1 entries (value at i==NV is 0)
#define SCAN_B 512
__global__ void scan_partial_kernel() {
    __shared__ int s[SCAN_B];
    int i = blockIdx.x * SCAN_B + threadIdx.x;
    int v = (i < NV) ? g_deg[i] : 0;
    s[threadIdx.x] = v;
    __syncthreads();
    for (int off = SCAN_B / 2; off > 0; off >>= 1) {
        if (threadIdx.x < off) s[threadIdx.x] += s[threadIdx.x + off];
        __syncthreads();
    }
    if (threadIdx.x == 0) g_blocksum[blockIdx.x] = s[0];
}

__global__ void scan_tops_kernel(int nblocks) {
    if (threadIdx.x == 0 && blockIdx.x == 0) {
        int acc = 0;
        for (int b = 0; b < nblocks; b++) {
            g_blockoff[b] = acc;
            acc += g_blocksum[b];
        }
    }
}

__global__ void scan_final_kernel() {
    __shared__ int s[SCAN_B];
    int i = blockIdx.x * SCAN_B + threadIdx.x;
    int v = (i < NV) ? g_deg[i] : 0;
    s[threadIdx.x] = v;
    __syncthreads();
    // Hillis-Steele inclusive scan
    for (int off = 1; off < SCAN_B; off <<= 1) {
        int t = (threadIdx.x >= off) ? s[threadIdx.x - off] : 0;
        __syncthreads();
        s[threadIdx.x] += t;
        __syncthreads();
    }
    int excl = s[threadIdx.x] - v;
    if (i <= NV) g_rowptr[i] = g_blockoff[blockIdx.x] + excl;
}

__global__ void fill_kernel(const int* __restrict__ src,
                            const int* __restrict__ dst) {
    int e = blockIdx.x * blockDim.x + threadIdx.x;
    if (e < EE) {
        int d = dst[e];
        int pos = g_rowptr[d] + atomicAdd(&g_fill[d], 1);
        g_col[pos] = src[e];
    }
}

// ---------------- per-layer kernels ------------------------------------------
// 9-tap 'same' conv along T for each node row. 2 nodes per 256-thread block.
__global__ void conv_kernel(const float* __restrict__ x,
                            const float* __restrict__ w,  // conv_w base
                            const float* __restrict__ b,  // conv_b base
                            int layer) {
    __shared__ float s[2][TT + 8];
    int ln = threadIdx.x >> 7;        // node within block (0/1)
    int t  = threadIdx.x & 127;
    int n  = blockIdx.x * 2 + ln;
    const float* xr = x + (size_t)n * TT;
    s[ln][t + 4] = xr[t];
    if (t < 4) { s[ln][t] = 0.0f; s[ln][t + TT + 4] = 0.0f; }
    __syncthreads();
    float wv[KK];
#pragma unroll
    for (int k = 0; k < KK; k++) wv[k] = __ldg(&w[layer * KK + k]);
    float acc = __ldg(&b[layer]);
#pragma unroll
    for (int k = 0; k < KK; k++) acc += wv[k] * s[ln][t + k];
    g_h[(size_t)n * TT + t] = acc;
}

// One warp per destination node: self-loop + neighbor gather, mean, ReLU.
// Lane l owns float4 at columns [4l, 4l+4).
__global__ void agg_kernel(float* __restrict__ xout) {
    int warp = (blockIdx.x * blockDim.x + threadIdx.x) >> 5;
    int lane = threadIdx.x & 31;
    if (warp >= NV) return;
    const float4* h4 = reinterpret_cast<const float4*>(g_h);
    float4 acc = h4[(size_t)warp * 32 + lane];   // self loop
    int beg = g_rowptr[warp];
    int end = g_rowptr[warp + 1];
    for (int e = beg; e < end; e++) {
        int srcn = g_col[e];
        float4 v = h4[(size_t)srcn * 32 + lane];
        acc.x += v.x; acc.y += v.y; acc.z += v.z; acc.w += v.w;
    }
    float inv = 1.0f / (float)(end - beg + 1);
    float4 r;
    r.x = fmaxf(acc.x * inv, 0.0f);
    r.y = fmaxf(acc.y * inv, 0.0f);
    r.z = fmaxf(acc.z * inv, 0.0f);
    r.w = fmaxf(acc.w * inv, 0.0f);
    reinterpret_cast<float4*>(xout)[(size_t)warp * 32 + lane] = r;
}

// Final projection: y[a, c] = sum_b flat[a*NV + b] * W[c*NV + b] + b_out[c]
// flat is g_x reinterpreted (reshape semantics, NOT transpose).
__global__ void out_kernel(const float* __restrict__ Wout,
                           const float* __restrict__ bout,
                           float* __restrict__ y) {
    int a = blockIdx.x;                 // 0..127
    const float* flat = g_x + (size_t)a * NV;
    float a0 = 0.0f, a1 = 0.0f, a2 = 0.0f;
    for (int bidx = threadIdx.x; bidx < NV; bidx += blockDim.x) {
        float v = flat[bidx];
        a0 += v * __ldg(&Wout[0 * NV + bidx]);
        a1 += v * __ldg(&Wout[1 * NV + bidx]);
        a2 += v * __ldg(&Wout[2 * NV + bidx]);
    }
    __shared__ float s0[256], s1[256], s2[256];
    s0[threadIdx.x] = a0; s1[threadIdx.x] = a1; s2[threadIdx.x] = a2;
    __syncthreads();
    for (int off = 128; off > 0; off >>= 1) {
        if (threadIdx.x < off) {
            s0[threadIdx.x] += s0[threadIdx.x + off];
            s1[threadIdx.x] += s1[threadIdx.x + off];
            s2[threadIdx.x] += s2[threadIdx.x + off];
        }
        __syncthreads();
    }
    if (threadIdx.x == 0) {
        y[a * 3 + 0] = s0[0] + __ldg(&bout[0]);
        y[a * 3 + 1] = s1[0] + __ldg(&bout[1]);
        y[a * 3 + 2] = s2[0] + __ldg(&bout[2]);
    }
}

// ---------------- launch -----------------------------------------------------
extern "C" void kernel_launch(void* const* d_in, const int* in_sizes, int n_in,
                              void* d_out, int out_size) {
    const float* x_in    = (const float*)d_in[0];          // [N, T]
    const int*   ei      = (const int*)d_in[1];            // [2, E]
    const float* conv_w  = (const float*)d_in[2];          // [L,1,1,K]
    const float* conv_b  = (const float*)d_in[3];          // [L,1]
    const float* W_out   = (const float*)d_in[4];          // [3, N]
    const float* b_out   = (const float*)d_in[5];          // [3]
    float* y = (float*)d_out;                              // [T, 3]

    const int* src = ei;        // edge_index[0]
    const int* dst = ei + EE;   // edge_index[1]

    // resolve symbol addresses for ping-pong
    float* xbuf;
    cudaGetSymbolAddress((void**)&xbuf, g_x);

    const int scan_blocks = (NV + 1 + SCAN_B - 1) / SCAN_B;   // 196

    // ---- CSR build (once per launch) ----
    zero_counts_kernel<<<(NV + 255) / 256, 256>>>();
    hist_kernel<<<(EE + 255) / 256, 256>>>(dst);
    scan_partial_kernel<<<scan_blocks, SCAN_B>>>();
    scan_tops_kernel<<<1, 32>>>(scan_blocks);
    scan_final_kernel<<<scan_blocks, SCAN_B>>>();
    fill_kernel<<<(EE + 255) / 256, 256>>>(src, dst);

    const int agg_blocks = (NV * 32 + 255) / 256;             // 8 warps/block

    // ---- layer 0 ----
    conv_kernel<<<NV / 2, 256>>>(x_in, conv_w, conv_b, 0);
    agg_kernel<<<agg_blocks, 256>>>(xbuf);
    // ---- layer 1 ----
    conv_kernel<<<NV / 2, 256>>>(xbuf, conv_w, conv_b, 1);
    agg_kernel<<<agg_blocks, 256>>>(xbuf);
    // ---- layer 2 ----
    conv_kernel<<<NV / 2, 256>>>(xbuf, conv_w, conv_b, 2);
    agg_kernel<<<agg_blocks, 256>>>(xbuf);

    // ---- output projection ----
    out_kernel<<<TT, 256>>>(W_out, b_out, y);
}

// round 2
// speedup vs baseline: 1.3067x; 1.3067x over previous
#include <cuda_runtime.h>
#include <cuda_bf16.h>
#include <cstdint>

// Problem constants (fixed shapes per reference)
#define NV 100000      // vertices
#define TT 128         // temporal depth
#define EE 1600000     // edges
#define KK 9           // conv kernel
#define LL 3           // layers

// ---------------- scratch (device globals; no runtime allocation) -----------
__device__ float g_h [(size_t)NV * TT];    // ping
__device__ float g_h2[(size_t)NV * TT];    // pong
__device__ float g_x [(size_t)NV * TT];    // final activation (flat for out proj)
__device__ int   g_deg[NV];
__device__ int   g_fill[NV];
__device__ int   g_rowptr[NV + 1];
__device__ int   g_col[EE];
__device__ int   g_blocksum[256];
__device__ int   g_blockoff[256];

// ---------------- CSR build --------------------------------------------------
__global__ void zero_counts_kernel() {
    int i = blockIdx.x * blockDim.x + threadIdx.x;
    if (i < NV) { g_deg[i] = 0; g_fill[i] = 0; }
}

__global__ void hist_kernel(const int* __restrict__ dst) {
    int e = blockIdx.x * blockDim.x + threadIdx.x;
    if (e < EE) atomicAdd(&g_deg[dst[e]], 1);
}

#define SCAN_B 512
__global__ void scan_partial_kernel() {
    __shared__ int s[SCAN_B];
    int i = blockIdx.x * SCAN_B + threadIdx.x;
    int v = (i < NV) ? g_deg[i] : 0;
    s[threadIdx.x] = v;
    __syncthreads();
    for (int off = SCAN_B / 2; off > 0; off >>= 1) {
        if (threadIdx.x < off) s[threadIdx.x] += s[threadIdx.x + off];
        __syncthreads();
    }
    if (threadIdx.x == 0) g_blocksum[blockIdx.x] = s[0];
}

// Parallel exclusive scan of up to 256 block sums (one 256-thread block).
__global__ void scan_tops_kernel(int nblocks) {
    __shared__ int s[256];
    int v = (threadIdx.x < nblocks) ? g_blocksum[threadIdx.x] : 0;
    s[threadIdx.x] = v;
    __syncthreads();
    for (int off = 1; off < 256; off <<= 1) {
        int t = (threadIdx.x >= off) ? s[threadIdx.x - off] : 0;
        __syncthreads();
        s[threadIdx.x] += t;
        __syncthreads();
    }
    if (threadIdx.x < nblocks) g_blockoff[threadIdx.x] = s[threadIdx.x] - v;
}

__global__ void scan_final_kernel() {
    __shared__ int s[SCAN_B];
    int i = blockIdx.x * SCAN_B + threadIdx.x;
    int v = (i < NV) ? g_deg[i] : 0;
    s[threadIdx.x] = v;
    __syncthreads();
    for (int off = 1; off < SCAN_B; off <<= 1) {
        int t = (threadIdx.x >= off) ? s[threadIdx.x - off] : 0;
        __syncthreads();
        s[threadIdx.x] += t;
        __syncthreads();
    }
    int excl = s[threadIdx.x] - v;
    if (i <= NV) g_rowptr[i] = g_blockoff[blockIdx.x] + excl;
}

__global__ void fill_kernel(const int* __restrict__ src,
                            const int* __restrict__ dst) {
    int e = blockIdx.x * blockDim.x + threadIdx.x;
    if (e < EE) {
        int d = dst[e];
        int pos = g_rowptr[d] + atomicAdd(&g_fill[d], 1);
        g_col[pos] = src[e];
    }
}

// ---------------- layer-0 conv ------------------------------------------------
__global__ void conv_kernel(const float* __restrict__ x,
                            const float* __restrict__ w,
                            const float* __restrict__ b,
                            float* __restrict__ hout) {
    __shared__ float s[2][TT + 8];
    int ln = threadIdx.x >> 7;
    int t  = threadIdx.x & 127;
    int n  = blockIdx.x * 2 + ln;
    s[ln][t + 4] = x[(size_t)n * TT + t];
    if (t < 4) { s[ln][t] = 0.0f; s[ln][t + TT + 4] = 0.0f; }
    __syncthreads();
    float wv[KK];
#pragma unroll
    for (int k = 0; k < KK; k++) wv[k] = __ldg(&w[k]);
    float acc = __ldg(&b[0]);
#pragma unroll
    for (int k = 0; k < KK; k++) acc += wv[k] * s[ln][t + k];
    hout[(size_t)n * TT + t] = acc;
}

// ---------------- gather helper -----------------------------------------------
// Warp-collective: lane owns float4 at cols [4*lane, 4*lane+4). Returns
// relu(mean) over {self} ∪ neighbors.
__device__ __forceinline__ float4 gather_mean_relu(int node, int lane,
                                                   const float4* __restrict__ h4) {
    float4 a0 = __ldg(&h4[(size_t)node * 32 + lane]);   // self loop
    float4 a1 = make_float4(0.f, 0.f, 0.f, 0.f);
    float4 a2 = make_float4(0.f, 0.f, 0.f, 0.f);
    float4 a3 = make_float4(0.f, 0.f, 0.f, 0.f);
    int beg = g_rowptr[node];
    int end = g_rowptr[node + 1];
    int e = beg;
    for (; e + 4 <= end; e += 4) {
        int s0 = g_col[e + 0], s1 = g_col[e + 1];
        int s2 = g_col[e + 2], s3 = g_col[e + 3];
        float4 v0 = __ldg(&h4[(size_t)s0 * 32 + lane]);
        float4 v1 = __ldg(&h4[(size_t)s1 * 32 + lane]);
        float4 v2 = __ldg(&h4[(size_t)s2 * 32 + lane]);
        float4 v3 = __ldg(&h4[(size_t)s3 * 32 + lane]);
        a0.x += v0.x; a0.y += v0.y; a0.z += v0.z; a0.w += v0.w;
        a1.x += v1.x; a1.y += v1.y; a1.z += v1.z; a1.w += v1.w;
        a2.x += v2.x; a2.y += v2.y; a2.z += v2.z; a2.w += v2.w;
        a3.x += v3.x; a3.y += v3.y; a3.z += v3.z; a3.w += v3.w;
    }
    for (; e < end; e++) {
        int s0 = g_col[e];
        float4 v0 = __ldg(&h4[(size_t)s0 * 32 + lane]);
        a0.x += v0.x; a0.y += v0.y; a0.z += v0.z; a0.w += v0.w;
    }
    a0.x += a1.x + a2.x + a3.x;
    a0.y += a1.y + a2.y + a3.y;
    a0.z += a1.z + a2.z + a3.z;
    a0.w += a1.w + a2.w + a3.w;
    float inv = 1.0f / (float)(end - beg + 1);
    float4 r;
    r.x = fmaxf(a0.x * inv, 0.0f);
    r.y = fmaxf(a0.y * inv, 0.0f);
    r.z = fmaxf(a0.z * inv, 0.0f);
    r.w = fmaxf(a0.w * inv, 0.0f);
    return r;
}

// ---------------- fused agg(+relu) + next-layer conv -------------------------
// The warp holds the node's full 128-value row; conv halo (+/-4) comes from
// neighbor lanes via shuffles. Eliminates the intermediate x buffer.
__global__ void agg_conv_kernel(const float4* __restrict__ hin,
                                float4* __restrict__ hout,
                                const float* __restrict__ w,   // conv_w + layer*K
                                const float* __restrict__ b) { // conv_b + layer
    int warp = (blockIdx.x * blockDim.x + threadIdx.x) >> 5;
    int lane = threadIdx.x & 31;
    if (warp >= NV) return;
    float4 r = gather_mean_relu(warp, lane, hin);

    const unsigned m = 0xffffffffu;
    float4 lf, rt;
    lf.x = __shfl_up_sync(m, r.x, 1);  lf.y = __shfl_up_sync(m, r.y, 1);
    lf.z = __shfl_up_sync(m, r.z, 1);  lf.w = __shfl_up_sync(m, r.w, 1);
    rt.x = __shfl_down_sync(m, r.x, 1); rt.y = __shfl_down_sync(m, r.y, 1);
    rt.z = __shfl_down_sync(m, r.z, 1); rt.w = __shfl_down_sync(m, r.w, 1);
    if (lane == 0)  lf = make_float4(0.f, 0.f, 0.f, 0.f);
    if (lane == 31) rt = make_float4(0.f, 0.f, 0.f, 0.f);

    float v[12] = { lf.x, lf.y, lf.z, lf.w,
                    r.x,  r.y,  r.z,  r.w,
                    rt.x, rt.y, rt.z, rt.w };
    float wv[KK];
#pragma unroll
    for (int k = 0; k < KK; k++) wv[k] = __ldg(&w[k]);
    float bv = __ldg(&b[0]);
    float4 o;
    o.x = bv; o.y = bv; o.z = bv; o.w = bv;
#pragma unroll
    for (int k = 0; k < KK; k++) {
        o.x += wv[k] * v[0 + k];
        o.y += wv[k] * v[1 + k];
        o.z += wv[k] * v[2 + k];
        o.w += wv[k] * v[3 + k];
    }
    hout[(size_t)warp * 32 + lane] = o;
}

// Final aggregation: relu(mean) only, into g_x (flat for the projection).
__global__ void agg_final_kernel(const float4* __restrict__ hin) {
    int warp = (blockIdx.x * blockDim.x + threadIdx.x) >> 5;
    int lane = threadIdx.x & 31;
    if (warp >= NV) return;
    float4 r = gather_mean_relu(warp, lane, hin);
    reinterpret_cast<float4*>(g_x)[(size_t)warp * 32 + lane] = r;
}

// ---------------- output projection ------------------------------------------
__global__ void init_y_kernel(const float* __restrict__ bout, float* __restrict__ y) {
    int i = threadIdx.x;
    if (i < TT * 3) y[i] = __ldg(&bout[i % 3]);
}

// Blocks tile the N dimension (chunk = 256). W chunk lives in registers
// (8 values per lane per row); warps stride over the 128 output rows.
#define OCHUNK 256
__global__ void out_kernel2(const float* __restrict__ Wout, float* __restrict__ y) {
    int n0 = blockIdx.x * OCHUNK;
    int C  = NV - n0; if (C > OCHUNK) C = OCHUNK;   // C is a multiple of 8 (NV=100000)
    int w  = threadIdx.x >> 5;
    int lane = threadIdx.x & 31;

    float w0[8], w1[8], w2[8];
#pragma unroll
    for (int q = 0; q < 8; q++) {
        int idx = lane * 8 + q;
        bool val = idx < C;
        int n = n0 + idx;
        w0[q] = val ? __ldg(&Wout[0 * NV + n]) : 0.f;
        w1[q] = val ? __ldg(&Wout[1 * NV + n]) : 0.f;
        w2[q] = val ? __ldg(&Wout[2 * NV + n]) : 0.f;
    }

    for (int a = w; a < TT; a += 8) {
        const float* xr = g_x + (size_t)a * NV + n0;
        float p0 = 0.f, p1 = 0.f, p2 = 0.f;
#pragma unroll
        for (int q4 = 0; q4 < 2; q4++) {
            int idx = lane * 8 + q4 * 4;
            if (idx < C) {
                float4 v = *reinterpret_cast<const float4*>(xr + idx);
                int q = q4 * 4;
                p0 += v.x * w0[q] + v.y * w0[q + 1] + v.z * w0[q + 2] + v.w * w0[q + 3];
                p1 += v.x * w1[q] + v.y * w1[q + 1] + v.z * w1[q + 2] + v.w * w1[q + 3];
                p2 += v.x * w2[q] + v.y * w2[q + 1] + v.z * w2[q + 2] + v.w * w2[q + 3];
            }
        }
#pragma unroll
        for (int off = 16; off > 0; off >>= 1) {
            p0 += __shfl_down_sync(0xffffffffu, p0, off);
            p1 += __shfl_down_sync(0xffffffffu, p1, off);
            p2 += __shfl_down_sync(0xffffffffu, p2, off);
        }
        if (lane == 0) {
            atomicAdd(&y[a * 3 + 0], p0);
            atomicAdd(&y[a * 3 + 1], p1);
            atomicAdd(&y[a * 3 + 2], p2);
        }
    }
}

// ---------------- launch -----------------------------------------------------
extern "C" void kernel_launch(void* const* d_in, const int* in_sizes, int n_in,
                              void* d_out, int out_size) {
    const float* x_in    = (const float*)d_in[0];
    const int*   ei      = (const int*)d_in[1];
    const float* conv_w  = (const float*)d_in[2];   // [L,1,1,K]
    const float* conv_b  = (const float*)d_in[3];   // [L,1]
    const float* W_out   = (const float*)d_in[4];   // [3, N]
    const float* b_out   = (const float*)d_in[5];   // [3]
    float* y = (float*)d_out;                       // [T, 3]

    const int* src = ei;
    const int* dst = ei + EE;

    float *hA, *hB;
    cudaGetSymbolAddress((void**)&hA, g_h);
    cudaGetSymbolAddress((void**)&hB, g_h2);

    const int scan_blocks = (NV + 1 + SCAN_B - 1) / SCAN_B;   // 196

    // CSR build
    zero_counts_kernel<<<(NV + 255) / 256, 256>>>();
    hist_kernel<<<(EE + 255) / 256, 256>>>(dst);
    scan_partial_kernel<<<scan_blocks, SCAN_B>>>();
    scan_tops_kernel<<<1, 256>>>(scan_blocks);
    scan_final_kernel<<<scan_blocks, SCAN_B>>>();
    fill_kernel<<<(EE + 255) / 256, 256>>>(src, dst);

    const int agg_blocks = (NV * 32 + 255) / 256;             // 8 warps/block

    // layer 0 conv
    conv_kernel<<<NV / 2, 256>>>(x_in, conv_w + 0 * KK, conv_b + 0, hA);
    // agg0 + conv1 fused
    agg_conv_kernel<<<agg_blocks, 256>>>((const float4*)hA, (float4*)hB,
                                         conv_w + 1 * KK, conv_b + 1);
    // agg1 + conv2 fused
    agg_conv_kernel<<<agg_blocks, 256>>>((const float4*)hB, (float4*)hA,
                                         conv_w + 2 * KK, conv_b + 2);
    // final agg -> g_x
    agg_final_kernel<<<agg_blocks, 256>>>((const float4*)hA);

    // projection
    init_y_kernel<<<1, 384>>>(b_out, y);
    out_kernel2<<<(NV + OCHUNK - 1) / OCHUNK, 256>>>(W_out, y);
}

// round 3
// speedup vs baseline: 1.4767x; 1.1301x over previous
#include <cuda_runtime.h>
#include <cuda_fp16.h>
#include <cstdint>

// Problem constants (fixed shapes per reference)
#define NV 100000      // vertices
#define TT 128         // temporal depth
#define EE 1600000     // edges
#define KK 9           // conv kernel
#define LL 3           // layers

// ---------------- scratch (device globals; no runtime allocation) -----------
__device__ __half g_hA[(size_t)NV * TT];   // ping  (fp16 activations)
__device__ __half g_hB[(size_t)NV * TT];   // pong
__device__ __half g_xh[(size_t)NV * TT];   // final activation (fp16, flat)
__device__ int    g_deg[NV];
__device__ int    g_fill[NV];
__device__ int    g_rowptr[NV + 1];
__device__ int    g_col[EE];
__device__ int    g_blocksum[256];
__device__ int    g_blockoff[256];

// ---------------- CSR build --------------------------------------------------
__global__ void zero_counts_kernel() {
    int i = blockIdx.x * blockDim.x + threadIdx.x;
    if (i < NV) { g_deg[i] = 0; g_fill[i] = 0; }
}

__global__ void hist_kernel(const int* __restrict__ dst) {
    int e = blockIdx.x * blockDim.x + threadIdx.x;
    if (e < EE) atomicAdd(&g_deg[dst[e]], 1);
}

#define SCAN_B 512
__global__ void scan_partial_kernel() {
    __shared__ int s[SCAN_B];
    int i = blockIdx.x * SCAN_B + threadIdx.x;
    int v = (i < NV) ? g_deg[i] : 0;
    s[threadIdx.x] = v;
    __syncthreads();
    for (int off = SCAN_B / 2; off > 0; off >>= 1) {
        if (threadIdx.x < off) s[threadIdx.x] += s[threadIdx.x + off];
        __syncthreads();
    }
    if (threadIdx.x == 0) g_blocksum[blockIdx.x] = s[0];
}

// Parallel exclusive scan of up to 256 block sums (one 256-thread block).
__global__ void scan_tops_kernel(int nblocks) {
    __shared__ int s[256];
    int v = (threadIdx.x < nblocks) ? g_blocksum[threadIdx.x] : 0;
    s[threadIdx.x] = v;
    __syncthreads();
    for (int off = 1; off < 256; off <<= 1) {
        int t = (threadIdx.x >= off) ? s[threadIdx.x - off] : 0;
        __syncthreads();
        s[threadIdx.x] += t;
        __syncthreads();
    }
    if (threadIdx.x < nblocks) g_blockoff[threadIdx.x] = s[threadIdx.x] - v;
}

__global__ void scan_final_kernel() {
    __shared__ int s[SCAN_B];
    int i = blockIdx.x * SCAN_B + threadIdx.x;
    int v = (i < NV) ? g_deg[i] : 0;
    s[threadIdx.x] = v;
    __syncthreads();
    for (int off = 1; off < SCAN_B; off <<= 1) {
        int t = (threadIdx.x >= off) ? s[threadIdx.x - off] : 0;
        __syncthreads();
        s[threadIdx.x] += t;
        __syncthreads();
    }
    int excl = s[threadIdx.x] - v;
    if (i <= NV) g_rowptr[i] = g_blockoff[blockIdx.x] + excl;
}

__global__ void fill_kernel(const int* __restrict__ src,
                            const int* __restrict__ dst) {
    int e = blockIdx.x * blockDim.x + threadIdx.x;
    if (e < EE) {
        int d = dst[e];
        int pos = g_rowptr[d] + atomicAdd(&g_fill[d], 1);
        g_col[pos] = src[e];
    }
}

// ---------------- fp16 helpers ------------------------------------------------
__device__ __forceinline__ float4 u2_to_f4(uint2 u) {
    __half2 p0 = *reinterpret_cast<__half2*>(&u.x);
    __half2 p1 = *reinterpret_cast<__half2*>(&u.y);
    float2 f0 = __half22float2(p0);
    float2 f1 = __half22float2(p1);
    return make_float4(f0.x, f0.y, f1.x, f1.y);
}

__device__ __forceinline__ uint2 f4_to_u2(float4 f) {
    __half2 p0 = __float22half2_rn(make_float2(f.x, f.y));
    __half2 p1 = __float22half2_rn(make_float2(f.z, f.w));
    uint2 u;
    u.x = *reinterpret_cast<unsigned*>(&p0);
    u.y = *reinterpret_cast<unsigned*>(&p1);
    return u;
}

#define ACC4(a, u) { float4 _f = u2_to_f4(u); \
    a.x += _f.x; a.y += _f.y; a.z += _f.z; a.w += _f.w; }

// ---------------- layer-0 conv (fp32 in -> fp16 out) --------------------------
__global__ void conv_kernel(const float* __restrict__ x,
                            const float* __restrict__ w,
                            const float* __restrict__ b,
                            __half* __restrict__ hout) {
    __shared__ float s[2][TT + 8];
    int ln = threadIdx.x >> 7;
    int t  = threadIdx.x & 127;
    int n  = blockIdx.x * 2 + ln;
    s[ln][t + 4] = x[(size_t)n * TT + t];
    if (t < 4) { s[ln][t] = 0.0f; s[ln][t + TT + 4] = 0.0f; }
    __syncthreads();
    float wv[KK];
#pragma unroll
    for (int k = 0; k < KK; k++) wv[k] = __ldg(&w[k]);
    float acc = __ldg(&b[0]);
#pragma unroll
    for (int k = 0; k < KK; k++) acc += wv[k] * s[ln][t + k];
    hout[(size_t)n * TT + t] = __float2half_rn(acc);
}

// ---------------- gather helper (fp16 rows, fp32 accum) -----------------------
// Lane owns 4 cols [4*lane, 4*lane+4) of a 128-col row = one uint2 (8B).
// Row stride in uint2 units = 32.
__device__ __forceinline__ float4 gather_mean_relu(int node, int lane,
                                                   const uint2* __restrict__ h2) {
    float4 a0 = u2_to_f4(__ldg(&h2[(size_t)node * 32 + lane]));  // self loop
    float4 a1 = make_float4(0.f, 0.f, 0.f, 0.f);
    float4 a2 = make_float4(0.f, 0.f, 0.f, 0.f);
    float4 a3 = make_float4(0.f, 0.f, 0.f, 0.f);
    int beg = g_rowptr[node];
    int end = g_rowptr[node + 1];
    int e = beg;
    // 8 loads in flight per iteration for MLP
    for (; e + 8 <= end; e += 8) {
        int s0 = g_col[e + 0], s1 = g_col[e + 1], s2 = g_col[e + 2], s3 = g_col[e + 3];
        int s4 = g_col[e + 4], s5 = g_col[e + 5], s6 = g_col[e + 6], s7 = g_col[e + 7];
        uint2 v0 = __ldg(&h2[(size_t)s0 * 32 + lane]);
        uint2 v1 = __ldg(&h2[(size_t)s1 * 32 + lane]);
        uint2 v2 = __ldg(&h2[(size_t)s2 * 32 + lane]);
        uint2 v3 = __ldg(&h2[(size_t)s3 * 32 + lane]);
        uint2 v4 = __ldg(&h2[(size_t)s4 * 32 + lane]);
        uint2 v5 = __ldg(&h2[(size_t)s5 * 32 + lane]);
        uint2 v6 = __ldg(&h2[(size_t)s6 * 32 + lane]);
        uint2 v7 = __ldg(&h2[(size_t)s7 * 32 + lane]);
        ACC4(a0, v0); ACC4(a1, v1); ACC4(a2, v2); ACC4(a3, v3);
        ACC4(a0, v4); ACC4(a1, v5); ACC4(a2, v6); ACC4(a3, v7);
    }
    for (; e + 4 <= end; e += 4) {
        int s0 = g_col[e + 0], s1 = g_col[e + 1], s2 = g_col[e + 2], s3 = g_col[e + 3];
        uint2 v0 = __ldg(&h2[(size_t)s0 * 32 + lane]);
        uint2 v1 = __ldg(&h2[(size_t)s1 * 32 + lane]);
        uint2 v2 = __ldg(&h2[(size_t)s2 * 32 + lane]);
        uint2 v3 = __ldg(&h2[(size_t)s3 * 32 + lane]);
        ACC4(a0, v0); ACC4(a1, v1); ACC4(a2, v2); ACC4(a3, v3);
    }
    for (; e < end; e++) {
        uint2 v0 = __ldg(&h2[(size_t)g_col[e] * 32 + lane]);
        ACC4(a0, v0);
    }
    a0.x += a1.x + a2.x + a3.x;
    a0.y += a1.y + a2.y + a3.y;
    a0.z += a1.z + a2.z + a3.z;
    a0.w += a1.w + a2.w + a3.w;
    float inv = 1.0f / (float)(end - beg + 1);
    float4 r;
    r.x = fmaxf(a0.x * inv, 0.0f);
    r.y = fmaxf(a0.y * inv, 0.0f);
    r.z = fmaxf(a0.z * inv, 0.0f);
    r.w = fmaxf(a0.w * inv, 0.0f);
    return r;
}

// ---------------- fused agg(+relu) + next-layer conv -------------------------
__global__ void agg_conv_kernel(const uint2* __restrict__ hin,
                                uint2* __restrict__ hout,
                                const float* __restrict__ w,
                                const float* __restrict__ b) {
    int warp = (blockIdx.x * blockDim.x + threadIdx.x) >> 5;
    int lane = threadIdx.x & 31;
    if (warp >= NV) return;
    float4 r = gather_mean_relu(warp, lane, hin);

    const unsigned m = 0xffffffffu;
    float4 lf, rt;
    lf.x = __shfl_up_sync(m, r.x, 1);  lf.y = __shfl_up_sync(m, r.y, 1);
    lf.z = __shfl_up_sync(m, r.z, 1);  lf.w = __shfl_up_sync(m, r.w, 1);
    rt.x = __shfl_down_sync(m, r.x, 1); rt.y = __shfl_down_sync(m, r.y, 1);
    rt.z = __shfl_down_sync(m, r.z, 1); rt.w = __shfl_down_sync(m, r.w, 1);
    if (lane == 0)  lf = make_float4(0.f, 0.f, 0.f, 0.f);
    if (lane == 31) rt = make_float4(0.f, 0.f, 0.f, 0.f);

    float v[12] = { lf.x, lf.y, lf.z, lf.w,
                    r.x,  r.y,  r.z,  r.w,
                    rt.x, rt.y, rt.z, rt.w };
    float wv[KK];
#pragma unroll
    for (int k = 0; k < KK; k++) wv[k] = __ldg(&w[k]);
    float bv = __ldg(&b[0]);
    float4 o;
    o.x = bv; o.y = bv; o.z = bv; o.w = bv;
#pragma unroll
    for (int k = 0; k < KK; k++) {
        o.x += wv[k] * v[0 + k];
        o.y += wv[k] * v[1 + k];
        o.z += wv[k] * v[2 + k];
        o.w += wv[k] * v[3 + k];
    }
    hout[(size_t)warp * 32 + lane] = f4_to_u2(o);
}

// Final aggregation: relu(mean) only, into g_xh (fp16, flat for projection).
__global__ void agg_final_kernel(const uint2* __restrict__ hin) {
    int warp = (blockIdx.x * blockDim.x + threadIdx.x) >> 5;
    int lane = threadIdx.x & 31;
    if (warp >= NV) return;
    float4 r = gather_mean_relu(warp, lane, hin);
    reinterpret_cast<uint2*>(g_xh)[(size_t)warp * 32 + lane] = f4_to_u2(r);
}

// ---------------- output projection ------------------------------------------
__global__ void init_y_kernel(const float* __restrict__ bout, float* __restrict__ y) {
    int i = threadIdx.x;
    if (i < TT * 3) y[i] = __ldg(&bout[i % 3]);
}

// Blocks tile the N dimension (chunk = 256); W chunk in registers; warps
// stride over the 128 output rows; x read as fp16.
#define OCHUNK 256
__global__ void out_kernel2(const float* __restrict__ Wout, float* __restrict__ y) {
    int n0 = blockIdx.x * OCHUNK;
    int C  = NV - n0; if (C > OCHUNK) C = OCHUNK;   // multiple of 8 (NV=100000)
    int w  = threadIdx.x >> 5;
    int lane = threadIdx.x & 31;

    float w0[8], w1[8], w2[8];
#pragma unroll
    for (int q = 0; q < 8; q++) {
        int idx = lane * 8 + q;
        bool val = idx < C;
        int n = n0 + idx;
        w0[q] = val ? __ldg(&Wout[0 * NV + n]) : 0.f;
        w1[q] = val ? __ldg(&Wout[1 * NV + n]) : 0.f;
        w2[q] = val ? __ldg(&Wout[2 * NV + n]) : 0.f;
    }

    for (int a = w; a < TT; a += 8) {
        const __half* xr = g_xh + (size_t)a * NV + n0;
        float p0 = 0.f, p1 = 0.f, p2 = 0.f;
#pragma unroll
        for (int q4 = 0; q4 < 2; q4++) {
            int idx = lane * 8 + q4 * 4;
            if (idx < C) {
                uint2 u = *reinterpret_cast<const uint2*>(xr + idx);
                float4 v = u2_to_f4(u);
                int q = q4 * 4;
                p0 += v.x * w0[q] + v.y * w0[q + 1] + v.z * w0[q + 2] + v.w * w0[q + 3];
                p1 += v.x * w1[q] + v.y * w1[q + 1] + v.z * w1[q + 2] + v.w * w1[q + 3];
                p2 += v.x * w2[q] + v.y * w2[q + 1] + v.z * w2[q + 2] + v.w * w2[q + 3];
            }
        }
#pragma unroll
        for (int off = 16; off > 0; off >>= 1) {
            p0 += __shfl_down_sync(0xffffffffu, p0, off);
            p1 += __shfl_down_sync(0xffffffffu, p1, off);
            p2 += __shfl_down_sync(0xffffffffu, p2, off);
        }
        if (lane == 0) {
            atomicAdd(&y[a * 3 + 0], p0);
            atomicAdd(&y[a * 3 + 1], p1);
            atomicAdd(&y[a * 3 + 2], p2);
        }
    }
}

// ---------------- launch -----------------------------------------------------
extern "C" void kernel_launch(void* const* d_in, const int* in_sizes, int n_in,
                              void* d_out, int out_size) {
    const float* x_in    = (const float*)d_in[0];
    const int*   ei      = (const int*)d_in[1];
    const float* conv_w  = (const float*)d_in[2];   // [L,1,1,K]
    const float* conv_b  = (const float*)d_in[3];   // [L,1]
    const float* W_out   = (const float*)d_in[4];   // [3, N]
    const float* b_out   = (const float*)d_in[5];   // [3]
    float* y = (float*)d_out;                       // [T, 3]

    const int* src = ei;
    const int* dst = ei + EE;

    __half *hA, *hB;
    cudaGetSymbolAddress((void**)&hA, g_hA);
    cudaGetSymbolAddress((void**)&hB, g_hB);

    const int scan_blocks = (NV + 1 + SCAN_B - 1) / SCAN_B;   // 196

    // CSR build
    zero_counts_kernel<<<(NV + 255) / 256, 256>>>();
    hist_kernel<<<(EE + 255) / 256, 256>>>(dst);
    scan_partial_kernel<<<scan_blocks, SCAN_B>>>();
    scan_tops_kernel<<<1, 256>>>(scan_blocks);
    scan_final_kernel<<<scan_blocks, SCAN_B>>>();
    fill_kernel<<<(EE + 255) / 256, 256>>>(src, dst);

    const int agg_blocks = (NV * 32 + 255) / 256;             // 8 warps/block

    // layer 0 conv (fp32 x -> fp16 h)
    conv_kernel<<<NV / 2, 256>>>(x_in, conv_w + 0 * KK, conv_b + 0, hA);
    // agg0 + conv1 fused
    agg_conv_kernel<<<agg_blocks, 256>>>((const uint2*)hA, (uint2*)hB,
                                         conv_w + 1 * KK, conv_b + 1);
    // agg1 + conv2 fused
    agg_conv_kernel<<<agg_blocks, 256>>>((const uint2*)hB, (uint2*)hA,
                                         conv_w + 2 * KK, conv_b + 2);
    // final agg -> g_xh (fp16)
    agg_final_kernel<<<agg_blocks, 256>>>((const uint2*)hA);

    // projection
    init_y_kernel<<<1, 384>>>(b_out, y);
    out_kernel2<<<(NV + OCHUNK - 1) / OCHUNK, 256>>>(W_out, y);
}